// round 4
// baseline (speedup 1.0000x reference)
#include <cuda_runtime.h>
#include <cuda_fp16.h>
#include <cstdint>

// ---------------------------------------------------------------------------
// Problem constants
// ---------------------------------------------------------------------------
#define N_IMG  16
#define CI     256
#define CO     256
#define HW     56
#define KTAP   13
#define PAD    6
#define HP     68           // 56 + 12
#define WPAD   76           // 56 + 12 padding + slack (s up to 12, w up to 55)

// Scratch (device globals; no cudaMalloc allowed)
__device__ __half g_xp[(size_t)N_IMG * HP * WPAD * CI];     // [n][hp][wp][ci]  ~42 MB
__device__ __half g_wt[(size_t)KTAP * KTAP * CO * CI];      // [tap][co][ci]    ~22 MB

// ---------------------------------------------------------------------------
// Helpers (arch-neutral PTX only: sm_80-class mma.sync / ldmatrix / cp.async)
// ---------------------------------------------------------------------------
__device__ __forceinline__ uint32_t smem_u32(const void* p) {
    uint32_t a;
    asm("{ .reg .u64 t; cvta.to.shared.u64 t, %1; cvt.u32.u64 %0, t; }" : "=r"(a) : "l"(p));
    return a;
}
__device__ __forceinline__ uint32_t swz(uint32_t off) {      // SW128: cols[4:6] ^= rows[7:9]
    return off ^ ((off >> 3) & 0x70);
}
__device__ __forceinline__ void cp16(uint32_t dst, const void* src) {
    asm volatile("cp.async.cg.shared.global [%0], [%1], 16;" :: "r"(dst), "l"(src) : "memory");
}
#define CP_COMMIT() asm volatile("cp.async.commit_group;" ::: "memory")
#define CP_WAIT(n)  asm volatile("cp.async.wait_group %0;" :: "n"(n) : "memory")

__device__ __forceinline__ void ldsm4(uint32_t* r, uint32_t addr) {
    asm volatile("ldmatrix.sync.aligned.m8n8.x4.shared.b16 {%0,%1,%2,%3}, [%4];"
                 : "=r"(r[0]), "=r"(r[1]), "=r"(r[2]), "=r"(r[3]) : "r"(addr));
}
__device__ __forceinline__ void ldsm2(uint32_t* r, uint32_t addr) {
    asm volatile("ldmatrix.sync.aligned.m8n8.x2.shared.b16 {%0,%1}, [%2];"
                 : "=r"(r[0]), "=r"(r[1]) : "r"(addr));
}
__device__ __forceinline__ void mma16816(float* d, const uint32_t* a, const uint32_t* b) {
    asm volatile(
        "mma.sync.aligned.m16n8k16.row.col.f32.f16.f16.f32 "
        "{%0,%1,%2,%3}, {%4,%5,%6,%7}, {%8,%9}, {%0,%1,%2,%3};"
        : "+f"(d[0]), "+f"(d[1]), "+f"(d[2]), "+f"(d[3])
        : "r"(a[0]), "r"(a[1]), "r"(a[2]), "r"(a[3]), "r"(b[0]), "r"(b[1]));
}

// ---------------------------------------------------------------------------
// Prepass 1: pad + transpose input NCHW f32 -> padded NHWC f16
// ---------------------------------------------------------------------------
__global__ void pad_input_kernel(const float* __restrict__ x) {
    const int nb = blockIdx.x;
    const int n  = nb / HP;
    const int hp = nb % HP;
    const int ci = threadIdx.x;
    const int h  = hp - PAD;
    const bool hv = (h >= 0) && (h < HW);
    const float* xrow = x + ((size_t)(n * CI + ci) * HW + (hv ? h : 0)) * HW;
    __half* dst = g_xp + ((size_t)(n * HP + hp) * WPAD) * CI + ci;
    #pragma unroll 4
    for (int wp = 0; wp < WPAD; ++wp) {
        const int w = wp - PAD;
        float v = 0.f;
        if (hv && w >= 0 && w < HW) v = xrow[w];
        dst[(size_t)wp * CI] = __float2half(v);
    }
}

// ---------------------------------------------------------------------------
// Prepass 2: weights (co,ci,13,13) f32 -> [tap][co][ci] f16
// ---------------------------------------------------------------------------
__global__ void conv_weight_kernel(const float* __restrict__ w) {
    const int id = blockIdx.x * 256 + threadIdx.x;   // co*256 + ci
    const int co = id >> 8;
    const int ci = id & 255;
    const float* src = w + (size_t)id * (KTAP * KTAP);
    __half* dst = g_wt + (size_t)co * CI + ci;
    #pragma unroll 13
    for (int t = 0; t < KTAP * KTAP; ++t)
        dst[(size_t)t * (CO * CI)] = __float2half(src[t]);
}

// ---------------------------------------------------------------------------
// Main: implicit-GEMM conv + BN + SiLU via mma.sync (m16n8k16 f16->f32)
// CTA tile: M=128 co x N=112 spatial (2 h-rows x 56 w, ZERO dead columns)
// K loop: 169 taps x 4 ci-chunks = 676 iters, 3-stage cp.async pipeline,
// one __syncthreads per iteration.
// grid = (448, 2): x = n*28 + htile, y = co block
// ---------------------------------------------------------------------------
#define A_BYTES     16384          // 128 rows x 128B
#define B_BYTES     14336          // 112 rows x 128B
#define STAGE_BYTES (A_BYTES + B_BYTES)     // 30720
#define NSTAGE      3
#define SMEM_DYN    (NSTAGE * STAGE_BYTES + 1024)

__global__ void __launch_bounds__(256, 2) conv_main_kernel(
    const float* __restrict__ gamma, const float* __restrict__ beta,
    const float* __restrict__ rmean, const float* __restrict__ rvar,
    float* __restrict__ out)
{
    extern __shared__ char smem_raw[];
    const uint32_t base = (smem_u32(smem_raw) + 1023u) & ~1023u;

    const int tid = threadIdx.x;
    const int l   = tid & 31;
    const int wid = tid >> 5;
    const int st  = blockIdx.x;
    const int cob = blockIdx.y;
    const int n   = st / 28;
    const int h0  = (st % 28) * 2;

    // ---- cp.async geometry: 8 chunks(16B) per 128B row, 256 thr -> 32 rows/pass
    // A: 128 rows (4 passes).  B: 112 rows (3 full passes + partial pass tid<128).
    const int c16  = tid & 7;
    const int row0 = tid >> 3;
    const char* a_src[4]; uint32_t a_dst[4];
    const char* b_src[4]; uint32_t b_dst[4];
    #pragma unroll
    for (int i = 0; i < 4; ++i) {
        const int rw = row0 + 32 * i;
        a_src[i] = (const char*)g_wt + (size_t)(cob * 128 + rw) * (CI * 2) + c16 * 16;
        a_dst[i] = swz((uint32_t)(rw * 128 + c16 * 16));
        if (rw < 112) {
            const int jr = rw / 56, wc = rw - jr * 56;
            b_src[i] = (const char*)g_xp
                     + (size_t)((n * HP + h0 + jr) * WPAD + wc) * (CI * 2) + c16 * 16;
            b_dst[i] = swz((uint32_t)(rw * 128 + c16 * 16)) + A_BYTES;
        } else { b_src[i] = nullptr; b_dst[i] = 0; }
    }
    const bool b_tail = (row0 + 96) < 112;   // tid < 128

    // Producer-side counters (no division in the loop)
    int p_kc = 0;                 // ci-chunk 0..3
    size_t p_woff = 0;            // tap * CO*CI*2
    size_t p_xoff = 0;            // (r*WPAD+s) * CI*2
    int p_s = 0;                  // tap column 0..12
    int p_ws = 0;                 // write stage

    auto issue = [&]() {
        const uint32_t sb = base + (uint32_t)p_ws * STAGE_BYTES;
        const size_t aoff = p_woff + (size_t)p_kc * 128;
        const size_t boff = p_xoff + (size_t)p_kc * 128;
        #pragma unroll
        for (int i = 0; i < 4; ++i) cp16(sb + a_dst[i], a_src[i] + aoff);
        #pragma unroll
        for (int i = 0; i < 3; ++i) cp16(sb + b_dst[i], b_src[i] + boff);
        if (b_tail) cp16(sb + b_dst[3], b_src[3] + boff);
        CP_COMMIT();
        if (++p_ws == NSTAGE) p_ws = 0;
        if (++p_kc == 4) {
            p_kc = 0;
            p_woff += (size_t)CO * CI * 2;
            if (++p_s == KTAP) { p_s = 0; p_xoff += (size_t)(WPAD - (KTAP - 1)) * CI * 2; }
            else               { p_xoff += (size_t)CI * 2; }
        }
    };

    // ---- MMA fragment geometry (warp grid 4x2, warp tile 32(M) x 56(N))
    const int wm = wid >> 1, wn = wid & 1;
    const int m0 = wm * 32, n0 = wn * 56;
    int arow[2]; uint32_t axor[2];
    int brow[3]; uint32_t bxor[3];
    const uint32_t hi_a = (uint32_t)((l >> 4) << 4);          // 16B chunk select
    const uint32_t hi_b = (uint32_t)(((l >> 3) & 1) << 4);
    #pragma unroll
    for (int mt = 0; mt < 2; ++mt) {
        const int r = m0 + 16 * mt + (l & 15);
        arow[mt] = r; axor[mt] = (uint32_t)((r & 7) << 4);
    }
    #pragma unroll
    for (int bt = 0; bt < 3; ++bt) {
        const int r = n0 + 16 * bt + (l & 7) + ((l >> 4) << 3);
        brow[bt] = r; bxor[bt] = (uint32_t)((r & 7) << 4);
    }
    // ldsm2 tail (rows n0+48..55): addresses from lanes 0..15 only
    const int lm = l & 15;
    const int trow = n0 + 48 + (lm & 7);
    const uint32_t txor = (uint32_t)((trow & 7) << 4);
    const uint32_t thi  = (uint32_t)(((lm >> 3) & 1) << 4);

    float acc[2][7][4];
    #pragma unroll
    for (int i = 0; i < 2; ++i)
        #pragma unroll
        for (int j = 0; j < 7; ++j)
            #pragma unroll
            for (int k = 0; k < 4; ++k) acc[i][j][k] = 0.f;

    auto compute = [&](int stage) {
        const uint32_t ab = base + (uint32_t)stage * STAGE_BYTES;
        const uint32_t bb = ab + A_BYTES;
        #pragma unroll
        for (int kk = 0; kk < 4; ++kk) {
            uint32_t a[2][4];
            #pragma unroll
            for (int mt = 0; mt < 2; ++mt)
                ldsm4(a[mt], ab + arow[mt] * 128 + (((uint32_t)kk * 32 + hi_a) ^ axor[mt]));
            #pragma unroll
            for (int bt = 0; bt < 3; ++bt) {
                uint32_t b[4];
                ldsm4(b, bb + brow[bt] * 128 + (((uint32_t)kk * 32 + hi_b) ^ bxor[bt]));
                #pragma unroll
                for (int mt = 0; mt < 2; ++mt) {
                    mma16816(acc[mt][2 * bt],     a[mt], b);
                    mma16816(acc[mt][2 * bt + 1], a[mt], b + 2);
                }
            }
            {   // tail 8 N-rows via ldmatrix.x2 (exactly one mma B operand)
                uint32_t b[2];
                ldsm2(b, bb + trow * 128 + (((uint32_t)kk * 32 + thi) ^ txor));
                #pragma unroll
                for (int mt = 0; mt < 2; ++mt)
                    mma16816(acc[mt][6], a[mt], b);
            }
        }
    };

    // ---- mainloop: 676 K-stages, 3-stage pipeline, one barrier per iter.
    issue();   // stage 0  (iter 0 data)
    issue();   // stage 1  (iter 1 data)
    int rs = 0;
    #pragma unroll 1
    for (int i = 0; i < 674; ++i) {
        CP_WAIT(1);
        __syncthreads();
        issue();                   // iter i+2 -> stage (i+2)%3
        compute(rs);
        if (++rs == NSTAGE) rs = 0;
    }
    CP_WAIT(0);
    __syncthreads();
    compute(rs); if (++rs == NSTAGE) rs = 0;   // iter 674
    compute(rs);                                // iter 675

    // ---- epilogue: BN + SiLU, registers -> NCHW fp32 (all lanes valid)
    const int h = h0 + wn;        // each warp column owns one full h row
    #pragma unroll
    for (int mt = 0; mt < 2; ++mt) {
        #pragma unroll
        for (int hf = 0; hf < 2; ++hf) {
            const int co = cob * 128 + m0 + 16 * mt + 8 * hf + (l >> 2);
            const float sc = gamma[co] * rsqrtf(rvar[co] + 1e-5f);
            const float sh = beta[co] - rmean[co] * sc;
            float* op = out + ((size_t)(n * CO + co) * HW + h) * HW;
            #pragma unroll
            for (int nt = 0; nt < 7; ++nt) {
                #pragma unroll
                for (int e = 0; e < 2; ++e) {
                    const int w = 8 * nt + 2 * (l & 3) + e;
                    const float y = acc[mt][nt][hf * 2 + e] * sc + sh;
                    op[w] = y / (1.f + __expf(-y));
                }
            }
        }
    }
}

// ---------------------------------------------------------------------------
// kernel_launch
// ---------------------------------------------------------------------------
extern "C" void kernel_launch(void* const* d_in, const int* in_sizes, int n_in,
                              void* d_out, int out_size)
{
    const float* x     = (const float*)d_in[0];
    const float* w     = (const float*)d_in[1];
    const float* gamma = (const float*)d_in[2];
    const float* beta  = (const float*)d_in[3];
    const float* rmean = (const float*)d_in[4];
    const float* rvar  = (const float*)d_in[5];
    float* out = (float*)d_out;

    cudaFuncSetAttribute(conv_main_kernel,
                         cudaFuncAttributeMaxDynamicSharedMemorySize, SMEM_DYN);

    pad_input_kernel<<<N_IMG * HP, 256>>>(x);
    conv_weight_kernel<<<(CO * CI) / 256, 256>>>(w);
    conv_main_kernel<<<dim3(N_IMG * 28, 2), 256, SMEM_DYN>>>(gamma, beta, rmean, rvar, out);
}

// round 5
// speedup vs baseline: 1.0545x; 1.0545x over previous
#include <cuda_runtime.h>
#include <cuda_fp16.h>
#include <cstdint>

// ---------------------------------------------------------------------------
// Problem constants
// ---------------------------------------------------------------------------
#define N_IMG  16
#define CI     256
#define CO     256
#define HW     56
#define KTAP   13
#define PAD    6
#define HP     68           // 56 + 12
#define WPAD   76           // 56 + 12 padding + slack

// Scratch (device globals; no cudaMalloc allowed)
__device__ __half g_xp[(size_t)N_IMG * HP * WPAD * CI];     // [n][hp][wp][ci]  ~42 MB
__device__ __half g_wt[(size_t)KTAP * KTAP * CO * CI];      // [tap][co][ci]    ~22 MB

// ---------------------------------------------------------------------------
// Helpers (arch-neutral PTX: mma.sync / ldmatrix / cp.async)
// ---------------------------------------------------------------------------
__device__ __forceinline__ uint32_t smem_u32(const void* p) {
    uint32_t a;
    asm("{ .reg .u64 t; cvta.to.shared.u64 t, %1; cvt.u32.u64 %0, t; }" : "=r"(a) : "l"(p));
    return a;
}
__device__ __forceinline__ uint32_t swz(uint32_t off) {      // SW128: bits[4:6] ^= bits[7:9]
    return off ^ ((off >> 3) & 0x70);
}
__device__ __forceinline__ void cp16(uint32_t dst, const void* src) {
    asm volatile("cp.async.cg.shared.global [%0], [%1], 16;" :: "r"(dst), "l"(src) : "memory");
}
#define CP_COMMIT() asm volatile("cp.async.commit_group;" ::: "memory")
#define CP_WAIT(n)  asm volatile("cp.async.wait_group %0;" :: "n"(n) : "memory")

__device__ __forceinline__ void ldsm4(uint32_t* r, uint32_t addr) {
    asm volatile("ldmatrix.sync.aligned.m8n8.x4.shared.b16 {%0,%1,%2,%3}, [%4];"
                 : "=r"(r[0]), "=r"(r[1]), "=r"(r[2]), "=r"(r[3]) : "r"(addr));
}
__device__ __forceinline__ void ldsm2(uint32_t* r, uint32_t addr) {
    asm volatile("ldmatrix.sync.aligned.m8n8.x2.shared.b16 {%0,%1}, [%2];"
                 : "=r"(r[0]), "=r"(r[1]) : "r"(addr));
}
__device__ __forceinline__ void mma16816(float* d, const uint32_t* a, const uint32_t* b) {
    asm volatile(
        "mma.sync.aligned.m16n8k16.row.col.f32.f16.f16.f32 "
        "{%0,%1,%2,%3}, {%4,%5,%6,%7}, {%8,%9}, {%0,%1,%2,%3};"
        : "+f"(d[0]), "+f"(d[1]), "+f"(d[2]), "+f"(d[3])
        : "r"(a[0]), "r"(a[1]), "r"(a[2]), "r"(a[3]), "r"(b[0]), "r"(b[1]));
}

// ---------------------------------------------------------------------------
// Prepass 1: pad + transpose input NCHW f32 -> padded NHWC f16
// ---------------------------------------------------------------------------
__global__ void pad_input_kernel(const float* __restrict__ x) {
    const int nb = blockIdx.x;
    const int n  = nb / HP;
    const int hp = nb % HP;
    const int ci = threadIdx.x;
    const int h  = hp - PAD;
    const bool hv = (h >= 0) && (h < HW);
    const float* xrow = x + ((size_t)(n * CI + ci) * HW + (hv ? h : 0)) * HW;
    __half* dst = g_xp + ((size_t)(n * HP + hp) * WPAD) * CI + ci;
    #pragma unroll 4
    for (int wp = 0; wp < WPAD; ++wp) {
        const int w = wp - PAD;
        float v = 0.f;
        if (hv && w >= 0 && w < HW) v = xrow[w];
        dst[(size_t)wp * CI] = __float2half(v);
    }
}

// ---------------------------------------------------------------------------
// Prepass 2: weights (co,ci,13,13) f32 -> [tap][co][ci] f16
// ---------------------------------------------------------------------------
__global__ void conv_weight_kernel(const float* __restrict__ w) {
    const int id = blockIdx.x * 256 + threadIdx.x;   // co*256 + ci
    const int co = id >> 8;
    const int ci = id & 255;
    const float* src = w + (size_t)id * (KTAP * KTAP);
    __half* dst = g_wt + (size_t)co * CI + ci;
    #pragma unroll 13
    for (int t = 0; t < KTAP * KTAP; ++t)
        dst[(size_t)t * (CO * CI)] = __float2half(src[t]);
}

// ---------------------------------------------------------------------------
// Main: implicit-GEMM conv + BN + SiLU via mma.sync (m16n8k16 f16->f32)
// CTA: 128 threads (4 warps, grid 2x2), tile M=128 co x N=112 spatial
// Warp tile 64(M) x 56(N)  ->  smem reads 60KB/CTA-iter (was 88KB)
// K loop: 676 iters, 3-stage cp.async pipeline, one barrier per iter.
// grid = (448, 2)
// ---------------------------------------------------------------------------
#define A_BYTES     16384          // 128 rows x 128B
#define B_BYTES     14336          // 112 rows x 128B
#define STAGE_BYTES (A_BYTES + B_BYTES)     // 30720
#define NSTAGE      3
#define SMEM_DYN    (NSTAGE * STAGE_BYTES + 1024)

__global__ void __launch_bounds__(128, 2) conv_main_kernel(
    const float* __restrict__ gamma, const float* __restrict__ beta,
    const float* __restrict__ rmean, const float* __restrict__ rvar,
    float* __restrict__ out)
{
    extern __shared__ char smem_raw[];
    const uint32_t base = (smem_u32(smem_raw) + 1023u) & ~1023u;

    const int tid = threadIdx.x;
    const int l   = tid & 31;
    const int wid = tid >> 5;
    const int st  = blockIdx.x;
    const int cob = blockIdx.y;
    const int n   = st / 28;
    const int h0  = (st % 28) * 2;

    // ---- cp.async geometry: 8x16B chunks per 128B row; 128 thr = 16 rows/pass
    // A: 128 rows = 8 passes (stride 16 rows = +16KB gmem, +2048B smem)
    // B: 112 rows = 7 passes
    const int c16  = tid & 7;
    const int row0 = tid >> 3;                 // 0..15
    const char* a_base = (const char*)g_wt
        + (size_t)(cob * 128 + row0) * (CI * 2) + c16 * 16;
    const uint32_t a_dst0 = swz((uint32_t)(row0 * 128 + c16 * 16));
    // B: row j -> (h = h0 + j/56, w = j%56); offsets from one base pointer
    const char* b_base = (const char*)g_xp
        + (size_t)(n * HP + h0) * WPAD * (CI * 2) + c16 * 16;
    uint32_t b_off[7];
    #pragma unroll
    for (int i = 0; i < 7; ++i) {
        const int rj = row0 + 16 * i;
        const int jr = (rj >= 56);
        b_off[i] = (uint32_t)(rj + jr * (WPAD - 56)) * (CI * 2);
    }
    const uint32_t b_dst0 = swz((uint32_t)(row0 * 128 + c16 * 16)) + A_BYTES;

    // Producer counters (no division in loop)
    int p_kc = 0;                 // ci-chunk 0..3
    size_t p_woff = 0;            // tap * CO*CI*2
    size_t p_xoff = 0;            // (r*WPAD+s) * CI*2
    int p_s = 0;                  // tap col 0..12
    int p_ws = 0;                 // write stage

    auto issue = [&]() {
        const uint32_t sb = base + (uint32_t)p_ws * STAGE_BYTES;
        const char* asrc = a_base + p_woff + (size_t)p_kc * 128;
        const char* bsrc = b_base + p_xoff + (size_t)p_kc * 128;
        #pragma unroll
        for (int i = 0; i < 8; ++i)
            cp16(sb + a_dst0 + i * 2048u, asrc + (size_t)i * 16 * (CI * 2));
        #pragma unroll
        for (int i = 0; i < 7; ++i)
            cp16(sb + b_dst0 + i * 2048u, bsrc + b_off[i]);
        CP_COMMIT();
        if (++p_ws == NSTAGE) p_ws = 0;
        if (++p_kc == 4) {
            p_kc = 0;
            p_woff += (size_t)CO * CI * 2;
            if (++p_s == KTAP) { p_s = 0; p_xoff += (size_t)(WPAD - (KTAP - 1)) * CI * 2; }
            else               { p_xoff += (size_t)CI * 2; }
        }
    };

    // ---- MMA fragment geometry (warp grid 2x2, warp tile 64(M) x 56(N))
    const int wm = wid >> 1, wn = wid & 1;
    const int m0 = wm * 64, n0 = wn * 56;
    int arow[4]; uint32_t axor[4];
    int brow[3]; uint32_t bxor[3];
    const uint32_t hi_a = (uint32_t)((l >> 4) << 4);
    const uint32_t hi_b = (uint32_t)(((l >> 3) & 1) << 4);
    #pragma unroll
    for (int mt = 0; mt < 4; ++mt) {
        const int r = m0 + 16 * mt + (l & 15);
        arow[mt] = r; axor[mt] = (uint32_t)((r & 7) << 4);
    }
    #pragma unroll
    for (int bt = 0; bt < 3; ++bt) {
        const int r = n0 + 16 * bt + (l & 7) + ((l >> 4) << 3);
        brow[bt] = r; bxor[bt] = (uint32_t)((r & 7) << 4);
    }
    const int lm = l & 15;
    const int trow = n0 + 48 + (lm & 7);
    const uint32_t txor = (uint32_t)((trow & 7) << 4);
    const uint32_t thi  = (uint32_t)(((lm >> 3) & 1) << 4);

    float acc[4][7][4];
    #pragma unroll
    for (int i = 0; i < 4; ++i)
        #pragma unroll
        for (int j = 0; j < 7; ++j)
            #pragma unroll
            for (int k = 0; k < 4; ++k) acc[i][j][k] = 0.f;

    auto compute = [&](int stage) {
        const uint32_t ab = base + (uint32_t)stage * STAGE_BYTES;
        const uint32_t bb = ab + A_BYTES;
        #pragma unroll
        for (int kk = 0; kk < 4; ++kk) {
            uint32_t a[4][4];
            #pragma unroll
            for (int mt = 0; mt < 4; ++mt)
                ldsm4(a[mt], ab + arow[mt] * 128 + (((uint32_t)kk * 32 + hi_a) ^ axor[mt]));
            #pragma unroll
            for (int bt = 0; bt < 3; ++bt) {
                uint32_t b[4];
                ldsm4(b, bb + brow[bt] * 128 + (((uint32_t)kk * 32 + hi_b) ^ bxor[bt]));
                #pragma unroll
                for (int mt = 0; mt < 4; ++mt) {
                    mma16816(acc[mt][2 * bt],     a[mt], b);
                    mma16816(acc[mt][2 * bt + 1], a[mt], b + 2);
                }
            }
            {   // tail 8 N-rows (one mma B operand)
                uint32_t b[2];
                ldsm2(b, bb + trow * 128 + (((uint32_t)kk * 32 + thi) ^ txor));
                #pragma unroll
                for (int mt = 0; mt < 4; ++mt)
                    mma16816(acc[mt][6], a[mt], b);
            }
        }
    };

    // ---- mainloop: 676 K-stages, 3-stage pipeline, one barrier per iter.
    issue();   // stage 0
    issue();   // stage 1
    int rs = 0;
    #pragma unroll 1
    for (int i = 0; i < 674; ++i) {
        CP_WAIT(1);
        __syncthreads();
        issue();                   // iter i+2 -> stage (i+2)%3
        compute(rs);
        if (++rs == NSTAGE) rs = 0;
    }
    CP_WAIT(0);
    __syncthreads();
    compute(rs); if (++rs == NSTAGE) rs = 0;
    compute(rs);

    // ---- epilogue: BN + SiLU, registers -> NCHW fp32 (all lanes valid)
    const int h = h0 + wn;
    #pragma unroll
    for (int mt = 0; mt < 4; ++mt) {
        #pragma unroll
        for (int hf = 0; hf < 2; ++hf) {
            const int co = cob * 128 + m0 + 16 * mt + 8 * hf + (l >> 2);
            const float sc = gamma[co] * rsqrtf(rvar[co] + 1e-5f);
            const float sh = beta[co] - rmean[co] * sc;
            float* op = out + ((size_t)(n * CO + co) * HW + h) * HW;
            #pragma unroll
            for (int nt = 0; nt < 7; ++nt) {
                #pragma unroll
                for (int e = 0; e < 2; ++e) {
                    const int w = 8 * nt + 2 * (l & 3) + e;
                    const float y = acc[mt][nt][hf * 2 + e] * sc + sh;
                    op[w] = y / (1.f + __expf(-y));
                }
            }
        }
    }
}

// ---------------------------------------------------------------------------
// kernel_launch
// ---------------------------------------------------------------------------
extern "C" void kernel_launch(void* const* d_in, const int* in_sizes, int n_in,
                              void* d_out, int out_size)
{
    const float* x     = (const float*)d_in[0];
    const float* w     = (const float*)d_in[1];
    const float* gamma = (const float*)d_in[2];
    const float* beta  = (const float*)d_in[3];
    const float* rmean = (const float*)d_in[4];
    const float* rvar  = (const float*)d_in[5];
    float* out = (float*)d_out;

    cudaFuncSetAttribute(conv_main_kernel,
                         cudaFuncAttributeMaxDynamicSharedMemorySize, SMEM_DYN);

    pad_input_kernel<<<N_IMG * HP, 256>>>(x);
    conv_weight_kernel<<<(CO * CI) / 256, 256>>>(w);
    conv_main_kernel<<<dim3(N_IMG * 28, 2), 128, SMEM_DYN>>>(gamma, beta, rmean, rvar, out);
}

// round 6
// speedup vs baseline: 1.0740x; 1.0185x over previous
#include <cuda_runtime.h>
#include <cuda_fp16.h>
#include <cstdint>

// ---------------------------------------------------------------------------
// Problem constants
// ---------------------------------------------------------------------------
#define N_IMG  16
#define CI     256
#define CO     256
#define HW     56
#define KTAP   13
#define PAD    6
#define HP     68           // 56 + 12
#define WPAD   76           // 56 + 12 padding + slack

// Scratch (device globals; no cudaMalloc allowed)
__device__ __half g_xp[(size_t)N_IMG * HP * WPAD * CI];     // [n][hp][wp][ci]  ~42 MB
__device__ __half g_wt[(size_t)KTAP * KTAP * CO * CI];      // [tap][co][ci]    ~22 MB

// ---------------------------------------------------------------------------
// Helpers (arch-neutral PTX: mma.sync / ldmatrix / cp.async)
// ---------------------------------------------------------------------------
__device__ __forceinline__ uint32_t smem_u32(const void* p) {
    uint32_t a;
    asm("{ .reg .u64 t; cvta.to.shared.u64 t, %1; cvt.u32.u64 %0, t; }" : "=r"(a) : "l"(p));
    return a;
}
__device__ __forceinline__ uint32_t swz(uint32_t off) {      // SW128: bits[4:6] ^= bits[7:9]
    return off ^ ((off >> 3) & 0x70);
}
__device__ __forceinline__ void cp16(uint32_t dst, const void* src) {
    asm volatile("cp.async.cg.shared.global [%0], [%1], 16;" :: "r"(dst), "l"(src) : "memory");
}
#define CP_COMMIT() asm volatile("cp.async.commit_group;" ::: "memory")
#define CP_WAIT(n)  asm volatile("cp.async.wait_group %0;" :: "n"(n) : "memory")

__device__ __forceinline__ void ldsm4(uint32_t* r, uint32_t addr) {
    asm volatile("ldmatrix.sync.aligned.m8n8.x4.shared.b16 {%0,%1,%2,%3}, [%4];"
                 : "=r"(r[0]), "=r"(r[1]), "=r"(r[2]), "=r"(r[3]) : "r"(addr));
}
__device__ __forceinline__ void ldsm2(uint32_t* r, uint32_t addr) {
    asm volatile("ldmatrix.sync.aligned.m8n8.x2.shared.b16 {%0,%1}, [%2];"
                 : "=r"(r[0]), "=r"(r[1]) : "r"(addr));
}
__device__ __forceinline__ void mma16816(float* d, const uint32_t* a, const uint32_t* b) {
    asm volatile(
        "mma.sync.aligned.m16n8k16.row.col.f32.f16.f16.f32 "
        "{%0,%1,%2,%3}, {%4,%5,%6,%7}, {%8,%9}, {%0,%1,%2,%3};"
        : "+f"(d[0]), "+f"(d[1]), "+f"(d[2]), "+f"(d[3])
        : "r"(a[0]), "r"(a[1]), "r"(a[2]), "r"(a[3]), "r"(b[0]), "r"(b[1]));
}

// ---------------------------------------------------------------------------
// Prepass 1: pad + transpose input NCHW f32 -> padded NHWC f16
// block = 128 threads (one (n,hp) row; 2 ci per thread, half2 stores)
// ---------------------------------------------------------------------------
__global__ void pad_input_kernel(const float* __restrict__ x) {
    const int nb = blockIdx.x;
    const int n  = nb / HP;
    const int hp = nb % HP;
    const int h  = hp - PAD;
    const bool hv = (h >= 0) && (h < HW);
    const int ci0 = threadIdx.x * 2;
    const float* r0 = x + ((size_t)(n * CI + ci0) * HW + (hv ? h : 0)) * HW;
    const float* r1 = r0 + (size_t)HW * HW;
    __half2* dst = (__half2*)(g_xp + ((size_t)(n * HP + hp) * WPAD) * CI + ci0);
    #pragma unroll 4
    for (int wp = 0; wp < WPAD; ++wp) {
        const int w = wp - PAD;
        float v0 = 0.f, v1 = 0.f;
        if (hv && w >= 0 && w < HW) { v0 = r0[w]; v1 = r1[w]; }
        dst[(size_t)wp * (CI / 2)] = __floats2half2_rn(v0, v1);
    }
}

// ---------------------------------------------------------------------------
// Prepass 2: weights (co,ci,13,13) f32 -> [tap][co][ci] f16, smem transpose
// grid (CO, 13): block handles one co x one 13-tap row; coalesced both ways
// ---------------------------------------------------------------------------
#define WSROW 258   // halves per smem tap-row (256 + 2 pad: conflict-free fill)
__global__ void conv_weight_kernel(const float* __restrict__ w) {
    __shared__ __half s[13 * WSROW];
    const int co = blockIdx.x;
    const int kr = blockIdx.y;             // tap row 0..12
    const int tid = threadIdx.x;
    const float* src = w + ((size_t)co * CI) * (KTAP * KTAP) + kr * KTAP;
    // fill: 3328 elems, j = ci*13 + tap (contiguous 13-float runs per ci)
    #pragma unroll
    for (int k = 0; k < 13; ++k) {
        const int j  = tid + k * 256;
        const int ci = j / 13;
        const int tp = j - ci * 13;
        s[tp * WSROW + ci] = __float2half(src[(size_t)ci * (KTAP * KTAP) + tp]);
    }
    __syncthreads();
    // drain: per tap, 256 coalesced half stores (threads = ci)
    __half* dst = g_wt + (size_t)(kr * KTAP) * (CO * CI) + (size_t)co * CI + tid;
    #pragma unroll
    for (int tp = 0; tp < 13; ++tp)
        dst[(size_t)tp * (CO * CI)] = s[tp * WSROW + tid];
}

// ---------------------------------------------------------------------------
// Main: implicit-GEMM conv + BN + SiLU via mma.sync (m16n8k16 f16->f32)
// CTA: 128 threads (4 warps 2x2), tile M=128 co x N=112 spatial
// Warp tile 64(M) x 56(N); K loop 676 iters, 3-stage cp.async pipeline,
// one barrier per iter; A fragments register-double-buffered across kk.
// grid = (448, 2)
// ---------------------------------------------------------------------------
#define A_BYTES     16384          // 128 rows x 128B
#define B_BYTES     14336          // 112 rows x 128B
#define STAGE_BYTES (A_BYTES + B_BYTES)     // 30720
#define NSTAGE      3
#define SMEM_DYN    (NSTAGE * STAGE_BYTES + 1024)

__global__ void __launch_bounds__(128, 2) conv_main_kernel(
    const float* __restrict__ gamma, const float* __restrict__ beta,
    const float* __restrict__ rmean, const float* __restrict__ rvar,
    float* __restrict__ out)
{
    extern __shared__ char smem_raw[];
    const uint32_t base = (smem_u32(smem_raw) + 1023u) & ~1023u;

    const int tid = threadIdx.x;
    const int l   = tid & 31;
    const int wid = tid >> 5;
    const int st  = blockIdx.x;
    const int cob = blockIdx.y;
    const int n   = st / 28;
    const int h0  = (st % 28) * 2;

    // ---- cp.async geometry: 8x16B chunks per 128B row; 128 thr = 16 rows/pass
    const int c16  = tid & 7;
    const int row0 = tid >> 3;                 // 0..15
    const char* a_base = (const char*)g_wt
        + (size_t)(cob * 128 + row0) * (CI * 2) + c16 * 16;
    const uint32_t a_dst0 = swz((uint32_t)(row0 * 128 + c16 * 16));
    const char* b_base = (const char*)g_xp
        + (size_t)(n * HP + h0) * WPAD * (CI * 2) + c16 * 16;
    uint32_t b_off[7];
    #pragma unroll
    for (int i = 0; i < 7; ++i) {
        const int rj = row0 + 16 * i;
        const int jr = (rj >= 56);
        b_off[i] = (uint32_t)(rj + jr * (WPAD - 56)) * (CI * 2);
    }
    const uint32_t b_dst0 = swz((uint32_t)(row0 * 128 + c16 * 16)) + A_BYTES;

    // Producer counters (no division in loop)
    int p_kc = 0;
    size_t p_woff = 0;
    size_t p_xoff = 0;
    int p_s = 0;
    int p_ws = 0;

    auto issue = [&]() {
        const uint32_t sb = base + (uint32_t)p_ws * STAGE_BYTES;
        const char* asrc = a_base + p_woff + (size_t)p_kc * 128;
        const char* bsrc = b_base + p_xoff + (size_t)p_kc * 128;
        #pragma unroll
        for (int i = 0; i < 8; ++i)
            cp16(sb + a_dst0 + i * 2048u, asrc + (size_t)i * 16 * (CI * 2));
        #pragma unroll
        for (int i = 0; i < 7; ++i)
            cp16(sb + b_dst0 + i * 2048u, bsrc + b_off[i]);
        CP_COMMIT();
        if (++p_ws == NSTAGE) p_ws = 0;
        if (++p_kc == 4) {
            p_kc = 0;
            p_woff += (size_t)CO * CI * 2;
            if (++p_s == KTAP) { p_s = 0; p_xoff += (size_t)(WPAD - (KTAP - 1)) * CI * 2; }
            else               { p_xoff += (size_t)CI * 2; }
        }
    };

    // ---- MMA fragment geometry (warp grid 2x2, warp tile 64(M) x 56(N))
    const int wm = wid >> 1, wn = wid & 1;
    const int m0 = wm * 64, n0 = wn * 56;
    uint32_t a_addr[4];            // per-mt base addr (kk component added later)
    int brow[3]; uint32_t bxor[3];
    const uint32_t hi_a = (uint32_t)((l >> 4) << 4);
    const uint32_t hi_b = (uint32_t)(((l >> 3) & 1) << 4);
    #pragma unroll
    for (int mt = 0; mt < 4; ++mt) {
        const int r = m0 + 16 * mt + (l & 15);
        a_addr[mt] = (uint32_t)(r * 128) | 0x80000000u;     // marker unused; replaced below
        a_addr[mt] = (uint32_t)(r * 128);
        a_addr[mt] = a_addr[mt];                             // keep simple
        a_addr[mt] = (uint32_t)(r * 128);
        a_addr[mt] ^= 0;                                     // no-op
        a_addr[mt] = (uint32_t)(r * 128);
        // store row + per-row xor separately:
        a_addr[mt] = (uint32_t)(r * 128) + 0;                // base byte offset of row
        a_addr[mt] |= ((uint32_t)((r & 7) << 4)) << 16;      // pack xor in hi half
    }
    #pragma unroll
    for (int bt = 0; bt < 3; ++bt) {
        const int r = n0 + 16 * bt + (l & 7) + ((l >> 4) << 3);
        brow[bt] = r; bxor[bt] = (uint32_t)((r & 7) << 4);
    }
    const int lm = l & 15;
    const int trow = n0 + 48 + (lm & 7);
    const uint32_t txor = (uint32_t)((trow & 7) << 4);
    const uint32_t thi  = (uint32_t)(((lm >> 3) & 1) << 4);

    float acc[4][7][4];
    #pragma unroll
    for (int i = 0; i < 4; ++i)
        #pragma unroll
        for (int j = 0; j < 7; ++j)
            #pragma unroll
            for (int k = 0; k < 4; ++k) acc[i][j][k] = 0.f;

    auto a_ld = [&](uint32_t ab, int kk, int mt, uint32_t* dst) {
        const uint32_t rowoff = a_addr[mt] & 0xFFFFu;
        const uint32_t rxor   = a_addr[mt] >> 16;
        ldsm4(dst, ab + rowoff + (((uint32_t)kk * 32 + hi_a) ^ rxor));
    };

    auto compute = [&](int stage) {
        const uint32_t ab = base + (uint32_t)stage * STAGE_BYTES;
        const uint32_t bb = ab + A_BYTES;
        uint32_t a[2][4][4];
        #pragma unroll
        for (int mt = 0; mt < 4; ++mt) a_ld(ab, 0, mt, a[0][mt]);
        #pragma unroll
        for (int kk = 0; kk < 4; ++kk) {
            const int cur = kk & 1;
            if (kk < 3) {
                #pragma unroll
                for (int mt = 0; mt < 4; ++mt) a_ld(ab, kk + 1, mt, a[cur ^ 1][mt]);
            }
            #pragma unroll
            for (int bt = 0; bt < 3; ++bt) {
                uint32_t b[4];
                ldsm4(b, bb + brow[bt] * 128 + (((uint32_t)kk * 32 + hi_b) ^ bxor[bt]));
                #pragma unroll
                for (int mt = 0; mt < 4; ++mt) {
                    mma16816(acc[mt][2 * bt],     a[cur][mt], b);
                    mma16816(acc[mt][2 * bt + 1], a[cur][mt], b + 2);
                }
            }
            {   // tail 8 N-rows (one mma B operand)
                uint32_t b[2];
                ldsm2(b, bb + trow * 128 + (((uint32_t)kk * 32 + thi) ^ txor));
                #pragma unroll
                for (int mt = 0; mt < 4; ++mt)
                    mma16816(acc[mt][6], a[cur][mt], b);
            }
        }
    };

    // ---- mainloop: 676 K-stages, 3-stage pipeline, one barrier per iter.
    issue();   // stage 0
    issue();   // stage 1
    int rs = 0;
    #pragma unroll 1
    for (int i = 0; i < 674; ++i) {
        CP_WAIT(1);
        __syncthreads();
        issue();                   // iter i+2 -> stage (i+2)%3
        compute(rs);
        if (++rs == NSTAGE) rs = 0;
    }
    CP_WAIT(0);
    __syncthreads();
    compute(rs); if (++rs == NSTAGE) rs = 0;
    compute(rs);

    // ---- epilogue: BN + SiLU, registers -> NCHW fp32 (all lanes valid)
    const int h = h0 + wn;
    #pragma unroll
    for (int mt = 0; mt < 4; ++mt) {
        #pragma unroll
        for (int hf = 0; hf < 2; ++hf) {
            const int co = cob * 128 + m0 + 16 * mt + 8 * hf + (l >> 2);
            const float sc = gamma[co] * rsqrtf(rvar[co] + 1e-5f);
            const float sh = beta[co] - rmean[co] * sc;
            float* op = out + ((size_t)(n * CO + co) * HW + h) * HW;
            #pragma unroll
            for (int nt = 0; nt < 7; ++nt) {
                #pragma unroll
                for (int e = 0; e < 2; ++e) {
                    const int w = 8 * nt + 2 * (l & 3) + e;
                    const float y = acc[mt][nt][hf * 2 + e] * sc + sh;
                    op[w] = y / (1.f + __expf(-y));
                }
            }
        }
    }
}

// ---------------------------------------------------------------------------
// kernel_launch
// ---------------------------------------------------------------------------
extern "C" void kernel_launch(void* const* d_in, const int* in_sizes, int n_in,
                              void* d_out, int out_size)
{
    const float* x     = (const float*)d_in[0];
    const float* w     = (const float*)d_in[1];
    const float* gamma = (const float*)d_in[2];
    const float* beta  = (const float*)d_in[3];
    const float* rmean = (const float*)d_in[4];
    const float* rvar  = (const float*)d_in[5];
    float* out = (float*)d_out;

    cudaFuncSetAttribute(conv_main_kernel,
                         cudaFuncAttributeMaxDynamicSharedMemorySize, SMEM_DYN);

    pad_input_kernel<<<N_IMG * HP, 128>>>(x);
    conv_weight_kernel<<<dim3(CO, KTAP), 256>>>(w);
    conv_main_kernel<<<dim3(N_IMG * 28, 2), 128, SMEM_DYN>>>(gamma, beta, rmean, rvar, out);
}